// round 1
// baseline (speedup 1.0000x reference)
#include <cuda_runtime.h>
#include <cstdint>

#define NN 100000
#define NE 600000
#define DK 128
#define AP 132   // padded row pitch for A smem tile (floats)

// ---------------- scratch (device globals; no allocation allowed) ----------------
__device__ float g_deg[NN];
__device__ float g_s  [(size_t)NN * DK];
__device__ float g_p  [(size_t)NN * DK];
__device__ float g_agg[(size_t)NN * DK];
__device__ float g_h  [(size_t)NN * DK];
__device__ float g_t  [(size_t)NN * DK];

// ---------------- small kernels ----------------
__global__ void zero_k(float4* __restrict__ p, int n4) {
    int i = blockIdx.x * blockDim.x + threadIdx.x;
    if (i < n4) p[i] = make_float4(0.f, 0.f, 0.f, 0.f);
}

__global__ void deg_k(const int* __restrict__ dst) {
    int e = blockIdx.x * blockDim.x + threadIdx.x;
    if (e < NE) atomicAdd(&g_deg[dst[e]], 1.0f);
}

__device__ __forceinline__ void red4(float* p, float4 v) {
    asm volatile("red.global.add.v4.f32 [%0], {%1, %2, %3, %4};"
                 :: "l"(p), "f"(v.x), "f"(v.y), "f"(v.z), "f"(v.w) : "memory");
}

// scatter: agg[dst[e]] += p[src[e]]   (row width DW, one warp per edge at DW=128)
template<int DW>
__global__ void scatter_k(const float* __restrict__ p, const int* __restrict__ src,
                          const int* __restrict__ dst, float* __restrict__ agg) {
    const int PV = DW / 4;
    int t = blockIdx.x * blockDim.x + threadIdx.x;
    int e = t / PV;
    if (e >= NE) return;
    int c = (t % PV) * 4;
    int sn = src[e];
    int dn = dst[e];
    float4 v = *reinterpret_cast<const float4*>(p + (size_t)sn * DW + c);
    red4(agg + (size_t)dn * DW + c, v);
}

// out = [relu](s + agg / max(deg,1))
template<int DW, bool RELU>
__global__ void combine_k(const float* __restrict__ s, const float* __restrict__ agg,
                          float* __restrict__ out) {
    const int PV = DW / 4;
    int t = blockIdx.x * blockDim.x + threadIdx.x;
    int r = t / PV;
    if (r >= NN) return;
    int c = (t % PV) * 4;
    float inv = 1.0f / fmaxf(g_deg[r], 1.0f);
    float4 a  = *reinterpret_cast<const float4*>(agg + (size_t)r * DW + c);
    float4 sv = *reinterpret_cast<const float4*>(s   + (size_t)r * DW + c);
    float4 o;
    o.x = sv.x + a.x * inv;
    o.y = sv.y + a.y * inv;
    o.z = sv.z + a.z * inv;
    o.w = sv.w + a.w * inv;
    if (RELU) {
        o.x = fmaxf(o.x, 0.f); o.y = fmaxf(o.y, 0.f);
        o.z = fmaxf(o.z, 0.f); o.w = fmaxf(o.w, 0.f);
    }
    *reinterpret_cast<float4*>(out + (size_t)r * DW + c) = o;
}

// ---------------- GEMM: C[M,BN] = [relu]( A[M,128] @ W[128,BN] (+ bias) ) ----------------
// 128-row tile per block, 256 threads, 8x8 (or 8x4) micro-tile via packed fma.rn.f32x2.
template<int BN, bool RELU, bool BIAS>
__global__ __launch_bounds__(256, 1)
void gemm_k(const float* __restrict__ A, const float* __restrict__ W,
            const float* __restrict__ bias, float* __restrict__ C, int M) {
    extern __shared__ float sm[];
    float* As = sm;              // [128][AP]
    float* Bs = sm + 128 * AP;   // [128][BN]

    const int tid = threadIdx.x;
    const int m0  = blockIdx.x * 128;

    // load A tile (coalesced float4), zero-pad OOB rows
#pragma unroll
    for (int i = 0; i < 16; ++i) {
        int idx = tid + i * 256;          // 0..4095 float4s
        int m   = idx >> 5;               // row 0..127
        int c4  = idx & 31;               // float4 within row
        float4 v = make_float4(0.f, 0.f, 0.f, 0.f);
        int gm = m0 + m;
        if (gm < M) v = *reinterpret_cast<const float4*>(A + (size_t)gm * DK + c4 * 4);
        *reinterpret_cast<float4*>(As + m * AP + c4 * 4) = v;
    }
    // load W tile
#pragma unroll
    for (int i = 0; i < (DK * BN / 4) / 256; ++i) {
        int idx = tid + i * 256;
        reinterpret_cast<float4*>(Bs)[idx] = reinterpret_cast<const float4*>(W)[idx];
    }
    __syncthreads();

    const int ty = tid >> 4;   // 0..15
    const int tx = tid & 15;   // 0..15
    const int c0 = tx * 4;
    constexpr int NP = BN / 32;          // f32x2 col-pairs: 128 -> 4, 64 -> 2

    unsigned long long acc[8][NP];
#pragma unroll
    for (int i = 0; i < 8; ++i)
#pragma unroll
        for (int j = 0; j < NP; ++j) acc[i][j] = 0ull;

#pragma unroll 4
    for (int k = 0; k < DK; ++k) {
        unsigned long long b2[NP];
        b2[0] = *reinterpret_cast<const unsigned long long*>(Bs + k * BN + c0);
        b2[1] = *reinterpret_cast<const unsigned long long*>(Bs + k * BN + c0 + 2);
        if constexpr (BN == 128) {
            b2[2] = *reinterpret_cast<const unsigned long long*>(Bs + k * BN + 64 + c0);
            b2[3] = *reinterpret_cast<const unsigned long long*>(Bs + k * BN + 64 + c0 + 2);
        }
#pragma unroll
        for (int i = 0; i < 8; ++i) {
            float a = As[(ty + 16 * i) * AP + k];
            unsigned long long a2;
            asm("mov.b64 %0, {%1, %1};" : "=l"(a2) : "f"(a));
#pragma unroll
            for (int j = 0; j < NP; ++j)
                asm("fma.rn.f32x2 %0, %1, %2, %0;" : "+l"(acc[i][j]) : "l"(a2), "l"(b2[j]));
        }
    }

    // epilogue
#pragma unroll
    for (int i = 0; i < 8; ++i) {
        int gm = m0 + ty + 16 * i;
        if (gm >= M) continue;
#pragma unroll
        for (int j = 0; j < NP; ++j) {
            int col = (j < 2) ? (c0 + 2 * j) : (64 + c0 + 2 * (j - 2));
            float x0, x1;
            asm("mov.b64 {%0, %1}, %2;" : "=f"(x0), "=f"(x1) : "l"(acc[i][j]));
            if (BIAS) { x0 += bias[col]; x1 += bias[col + 1]; }
            if (RELU) { x0 = fmaxf(x0, 0.f); x1 = fmaxf(x1, 0.f); }
            float2 o; o.x = x0; o.y = x1;
            *reinterpret_cast<float2*>(C + (size_t)gm * BN + col) = o;
        }
    }
}

// ---------------- launch ----------------
extern "C" void kernel_launch(void* const* d_in, const int* in_sizes, int n_in,
                              void* d_out, int out_size) {
    const float* x        = (const float*)d_in[0];
    const int*   src      = (const int*)  d_in[1];
    const int*   dst      = (const int*)  d_in[2];
    const float* w_self0  = (const float*)d_in[3];
    const float* b_self0  = (const float*)d_in[4];
    const float* w_neigh0 = (const float*)d_in[5];
    const float* fc_w     = (const float*)d_in[6];
    const float* fc_b     = (const float*)d_in[7];
    const float* fc2_w    = (const float*)d_in[8];
    const float* fc2_b    = (const float*)d_in[9];
    const float* w_self1  = (const float*)d_in[10];
    const float* b_self1  = (const float*)d_in[11];
    const float* w_neigh1 = (const float*)d_in[12];
    const float* w_self2  = (const float*)d_in[13];
    const float* b_self2  = (const float*)d_in[14];
    const float* w_neigh2 = (const float*)d_in[15];
    float* out = (float*)d_out;

    float *p_deg, *p_s, *p_p, *p_agg, *p_h, *p_t;
    cudaGetSymbolAddress((void**)&p_deg, g_deg);
    cudaGetSymbolAddress((void**)&p_s,   g_s);
    cudaGetSymbolAddress((void**)&p_p,   g_p);
    cudaGetSymbolAddress((void**)&p_agg, g_agg);
    cudaGetSymbolAddress((void**)&p_h,   g_h);
    cudaGetSymbolAddress((void**)&p_t,   g_t);

    const int smem128 = (128 * AP + 128 * 128) * 4;
    const int smem64  = (128 * AP + 128 * 64) * 4;
    cudaFuncSetAttribute(gemm_k<128, false, true >, cudaFuncAttributeMaxDynamicSharedMemorySize, smem128);
    cudaFuncSetAttribute(gemm_k<128, false, false>, cudaFuncAttributeMaxDynamicSharedMemorySize, smem128);
    cudaFuncSetAttribute(gemm_k<128, true,  true >, cudaFuncAttributeMaxDynamicSharedMemorySize, smem128);
    cudaFuncSetAttribute(gemm_k<64,  false, true >, cudaFuncAttributeMaxDynamicSharedMemorySize, smem64);
    cudaFuncSetAttribute(gemm_k<64,  false, false>, cudaFuncAttributeMaxDynamicSharedMemorySize, smem64);

    const int GB = (NN + 127) / 128;   // 782
    const int T  = 256;

    // degrees (graph is fixed across layers; compute once)
    zero_k<<<(NN / 4 + T - 1) / T, T>>>((float4*)p_deg, NN / 4);
    deg_k<<<(NE + T - 1) / T, T>>>(dst);

    // ---- layer 0: NGNN SAGEConv ----
    gemm_k<128, false, true ><<<GB, T, smem128>>>(x, w_self0,  b_self0, p_s, NN);
    gemm_k<128, false, false><<<GB, T, smem128>>>(x, w_neigh0, nullptr, p_p, NN);
    zero_k<<<(NN * 32 + T - 1) / T, T>>>((float4*)p_agg, NN * 32);
    scatter_k<128><<<((size_t)NE * 32 + T - 1) / T, T>>>(p_p, src, dst, p_agg);
    combine_k<128, true><<<(NN * 32 + T - 1) / T, T>>>(p_s, p_agg, p_h);
    gemm_k<128, true, true><<<GB, T, smem128>>>(p_h, fc_w,  fc_b,  p_t, NN);
    gemm_k<128, true, true><<<GB, T, smem128>>>(p_t, fc2_w, fc2_b, p_h, NN);

    // ---- layer 1: SAGEConv + ReLU ----
    gemm_k<128, false, true ><<<GB, T, smem128>>>(p_h, w_self1,  b_self1, p_s, NN);
    gemm_k<128, false, false><<<GB, T, smem128>>>(p_h, w_neigh1, nullptr, p_p, NN);
    zero_k<<<(NN * 32 + T - 1) / T, T>>>((float4*)p_agg, NN * 32);
    scatter_k<128><<<((size_t)NE * 32 + T - 1) / T, T>>>(p_p, src, dst, p_agg);
    combine_k<128, true><<<(NN * 32 + T - 1) / T, T>>>(p_s, p_agg, p_t);

    // ---- layer 2: SAGEConv (output, no activation), width 64 ----
    gemm_k<64, false, true ><<<GB, T, smem64>>>(p_t, w_self2,  b_self2, p_s, NN);
    gemm_k<64, false, false><<<GB, T, smem64>>>(p_t, w_neigh2, nullptr, p_p, NN);
    zero_k<<<(NN * 16 + T - 1) / T, T>>>((float4*)p_agg, NN * 16);
    scatter_k<64><<<((size_t)NE * 16 + T - 1) / T, T>>>(p_p, src, dst, p_agg);
    combine_k<64, false><<<(NN * 16 + T - 1) / T, T>>>(p_s, p_agg, out);
}

// round 3
// speedup vs baseline: 1.3460x; 1.3460x over previous
#include <cuda_runtime.h>
#include <cuda_bf16.h>
#include <mma.h>
#include <cstdint>

using namespace nvcuda;

#define NN 100000
#define NE 600000

// ---------------- scratch (device globals; no allocation allowed) ----------------
__device__ float g_a  [(size_t)NN * 128];
__device__ float g_b  [(size_t)NN * 128];
__device__ float g_p  [(size_t)NN * 128];
__device__ float g_deg[NN];

// split fp32 pair -> (hi bf16x2, lo bf16x2)
__device__ __forceinline__ void split2(float a, float b, uint32_t& hi, uint32_t& lo) {
    __nv_bfloat16 ha = __float2bfloat16(a), hb = __float2bfloat16(b);
    float ra = a - __bfloat162float(ha), rb = b - __bfloat162float(hb);
    __nv_bfloat16 la = __float2bfloat16(ra), lb = __float2bfloat16(rb);
    hi = ((uint32_t)__bfloat16_as_ushort(hb) << 16) | (uint32_t)__bfloat16_as_ushort(ha);
    lo = ((uint32_t)__bfloat16_as_ushort(lb) << 16) | (uint32_t)__bfloat16_as_ushort(la);
}

// ---------------- WMMA bf16 GEMM: C[M,BN] = [relu-in](A)[M,128] @ W[128,BN] (+bias) ----
// CTA tile 128 x BN, 256 threads (8 warps), warp tile 32 x BN/2.
// 2-term bf16 split, fp32 accumulate: A@W ~= Ahi@Whi + Ahi@Wlo + Alo@Whi.
template<int BN, bool RIN, bool BIAS>
__global__ __launch_bounds__(256)
void mm_k(const float* __restrict__ A, const float* __restrict__ Wt,
          const float* __restrict__ bias, float* __restrict__ C, int M)
{
    extern __shared__ char dsm[];
    constexpr int P   = 136;              // bf16 pitch (pad 8)
    constexpr int ASZ = 128 * P * 2;      // one A tile bytes
    constexpr int BSZ = BN  * P * 2;      // one B tile bytes
    constexpr int NC  = BN / 32;          // 16-col frags per warp (4 @128, 2 @64)
    constexpr int CP  = BN + 4;           // f32 epilogue pitch

    __nv_bfloat16* Ahi = reinterpret_cast<__nv_bfloat16*>(dsm);
    __nv_bfloat16* Alo = reinterpret_cast<__nv_bfloat16*>(dsm + ASZ);
    __nv_bfloat16* Bhi = reinterpret_cast<__nv_bfloat16*>(dsm + 2 * ASZ);
    __nv_bfloat16* Blo = reinterpret_cast<__nv_bfloat16*>(dsm + 2 * ASZ + BSZ);
    float*         Cs  = reinterpret_cast<float*>(dsm);

    const int tid = threadIdx.x;
    const int wid = tid >> 5;
    const int wr  = wid & 3;              // warp row 0..3  -> rows wr*32
    const int wc  = wid >> 2;             // warp col 0..1  -> cols wc*(BN/2)
    const int m0  = blockIdx.x * 128;

    // ---- A tile: f32 load (coalesced float4), optional relu, hi/lo split ----
#pragma unroll
    for (int i = 0; i < 16; ++i) {
        int idx = tid + i * 256;          // 4096 float4s
        int m   = idx >> 5;
        int k0  = (idx & 31) * 4;
        float4 v = make_float4(0.f, 0.f, 0.f, 0.f);
        int gm = m0 + m;
        if (gm < M) v = *reinterpret_cast<const float4*>(A + (size_t)gm * 128 + k0);
        if (RIN) { v.x = fmaxf(v.x, 0.f); v.y = fmaxf(v.y, 0.f); v.z = fmaxf(v.z, 0.f); v.w = fmaxf(v.w, 0.f); }
        uint32_t h0, l0, h1, l1;
        split2(v.x, v.y, h0, l0);
        split2(v.z, v.w, h1, l1);
        *reinterpret_cast<uint2*>(&Ahi[m * P + k0]) = make_uint2(h0, h1);
        *reinterpret_cast<uint2*>(&Alo[m * P + k0]) = make_uint2(l0, l1);
    }

    // ---- W tile: W[128(k), BN(n)] row-major -> Bs[n][k] (transpose), hi/lo split ----
#pragma unroll
    for (int i = 0; i < BN / 4; ++i) {
        int j  = tid + i * 256;           // 64*BN k-pair slots
        int n  = j % BN;
        int k0 = (j / BN) * 2;
        float w0 = Wt[(size_t)k0 * BN + n];
        float w1 = Wt[(size_t)(k0 + 1) * BN + n];
        uint32_t h, l;
        split2(w0, w1, h, l);
        *reinterpret_cast<uint32_t*>(&Bhi[n * P + k0]) = h;
        *reinterpret_cast<uint32_t*>(&Blo[n * P + k0]) = l;
    }
    __syncthreads();

    // ---- mainloop: 8 k-steps of 16, HMMA via wmma ----
    wmma::fragment<wmma::accumulator, 16, 16, 16, float> acc[2][NC];
#pragma unroll
    for (int i = 0; i < 2; ++i)
#pragma unroll
        for (int j = 0; j < NC; ++j) wmma::fill_fragment(acc[i][j], 0.0f);

#pragma unroll
    for (int ks = 0; ks < 8; ++ks) {
        const int k = ks * 16;
        wmma::fragment<wmma::matrix_a, 16, 16, 16, __nv_bfloat16, wmma::row_major> ah[2], al[2];
        wmma::fragment<wmma::matrix_b, 16, 16, 16, __nv_bfloat16, wmma::col_major> bh[NC], bl[NC];
#pragma unroll
        for (int i = 0; i < 2; ++i) {
            int m = wr * 32 + i * 16;
            wmma::load_matrix_sync(ah[i], &Ahi[m * P + k], P);
            wmma::load_matrix_sync(al[i], &Alo[m * P + k], P);
        }
#pragma unroll
        for (int j = 0; j < NC; ++j) {
            int n = wc * (BN / 2) + j * 16;
            wmma::load_matrix_sync(bh[j], &Bhi[n * P + k], P);
            wmma::load_matrix_sync(bl[j], &Blo[n * P + k], P);
        }
#pragma unroll
        for (int i = 0; i < 2; ++i)
#pragma unroll
            for (int j = 0; j < NC; ++j) {
                wmma::mma_sync(acc[i][j], ah[i], bh[j], acc[i][j]);
                wmma::mma_sync(acc[i][j], ah[i], bl[j], acc[i][j]);
                wmma::mma_sync(acc[i][j], al[i], bh[j], acc[i][j]);
            }
    }

    // ---- epilogue: frags -> smem f32 -> (bias) -> gmem float4 ----
    __syncthreads();   // done reading A/B smem
#pragma unroll
    for (int i = 0; i < 2; ++i)
#pragma unroll
        for (int j = 0; j < NC; ++j) {
            int m = wr * 32 + i * 16;
            int n = wc * (BN / 2) + j * 16;
            wmma::store_matrix_sync(&Cs[m * CP + n], acc[i][j], CP, wmma::mem_row_major);
        }
    __syncthreads();

#pragma unroll
    for (int i = 0; i < BN / 8; ++i) {
        int idx = tid + i * 256;          // 128 * BN/4 float4s
        int r   = idx / (BN / 4);
        int c   = (idx % (BN / 4)) * 4;
        int gm  = m0 + r;
        if (gm >= M) continue;
        float4 o = *reinterpret_cast<const float4*>(&Cs[r * CP + c]);
        if (BIAS) {
            o.x += bias[c + 0]; o.y += bias[c + 1];
            o.z += bias[c + 2]; o.w += bias[c + 3];
        }
        *reinterpret_cast<float4*>(C + (size_t)gm * BN + c) = o;
    }
}

// ---------------- graph kernels ----------------
__global__ void zero_k(float4* __restrict__ p, int n4) {
    int i = blockIdx.x * blockDim.x + threadIdx.x;
    if (i < n4) p[i] = make_float4(0.f, 0.f, 0.f, 0.f);
}

__global__ void deg_k(const int* __restrict__ dst) {
    int e = blockIdx.x * blockDim.x + threadIdx.x;
    if (e < NE) atomicAdd(&g_deg[dst[e]], 1.0f);
}

__global__ void inv_k() {
    int i = blockIdx.x * blockDim.x + threadIdx.x;
    if (i < NN) g_deg[i] = 1.0f / fmaxf(g_deg[i], 1.0f);
}

__device__ __forceinline__ void red4(float* p, float4 v) {
    asm volatile("red.global.add.v4.f32 [%0], {%1, %2, %3, %4};"
                 :: "l"(p), "f"(v.x), "f"(v.y), "f"(v.z), "f"(v.w) : "memory");
}

// out[dst[e]] += p[src[e]] * invdeg[dst[e]]   (out pre-initialized with self term + bias)
template<int DW>
__global__ void scatter_k(const float* __restrict__ p, const int* __restrict__ src,
                          const int* __restrict__ dst, float* __restrict__ out) {
    const int PV = DW / 4;
    int t = blockIdx.x * blockDim.x + threadIdx.x;
    int e = t / PV;
    if (e >= NE) return;
    int c = (t % PV) * 4;
    int sn = src[e];
    int dn = dst[e];
    float inv = g_deg[dn];
    float4 v = *reinterpret_cast<const float4*>(p + (size_t)sn * DW + c);
    v.x *= inv; v.y *= inv; v.z *= inv; v.w *= inv;
    red4(out + (size_t)dn * DW + c, v);
}

// ---------------- launch ----------------
extern "C" void kernel_launch(void* const* d_in, const int* in_sizes, int n_in,
                              void* d_out, int out_size) {
    const float* x        = (const float*)d_in[0];
    const int*   src      = (const int*)  d_in[1];
    const int*   dst      = (const int*)  d_in[2];
    const float* w_self0  = (const float*)d_in[3];
    const float* b_self0  = (const float*)d_in[4];
    const float* w_neigh0 = (const float*)d_in[5];
    const float* fc_w     = (const float*)d_in[6];
    const float* fc_b     = (const float*)d_in[7];
    const float* fc2_w    = (const float*)d_in[8];
    const float* fc2_b    = (const float*)d_in[9];
    const float* w_self1  = (const float*)d_in[10];
    const float* b_self1  = (const float*)d_in[11];
    const float* w_neigh1 = (const float*)d_in[12];
    const float* w_self2  = (const float*)d_in[13];
    const float* b_self2  = (const float*)d_in[14];
    const float* w_neigh2 = (const float*)d_in[15];
    float* out = (float*)d_out;

    float *p_a, *p_b, *p_p, *p_deg;
    cudaGetSymbolAddress((void**)&p_a,   g_a);
    cudaGetSymbolAddress((void**)&p_b,   g_b);
    cudaGetSymbolAddress((void**)&p_p,   g_p);
    cudaGetSymbolAddress((void**)&p_deg, g_deg);

    const int P128 = 136;
    const int s128 = (2 * 128 * P128 + 2 * 128 * P128) * 2;  // 139264
    const int s64  = (2 * 128 * P128 + 2 * 64  * P128) * 2;  // 104448
    cudaFuncSetAttribute(mm_k<128, false, true >, cudaFuncAttributeMaxDynamicSharedMemorySize, s128);
    cudaFuncSetAttribute(mm_k<128, false, false>, cudaFuncAttributeMaxDynamicSharedMemorySize, s128);
    cudaFuncSetAttribute(mm_k<128, true,  true >, cudaFuncAttributeMaxDynamicSharedMemorySize, s128);
    cudaFuncSetAttribute(mm_k<128, true,  false>, cudaFuncAttributeMaxDynamicSharedMemorySize, s128);
    cudaFuncSetAttribute(mm_k<64,  true,  true >, cudaFuncAttributeMaxDynamicSharedMemorySize, s64);
    cudaFuncSetAttribute(mm_k<64,  true,  false>, cudaFuncAttributeMaxDynamicSharedMemorySize, s64);

    const int GB = (NN + 127) / 128;   // 782
    const int T  = 256;

    // degrees -> inverse degrees (graph fixed across layers)
    zero_k<<<(NN / 4 + T - 1) / T, T>>>((float4*)p_deg, NN / 4);
    deg_k<<<(NE + T - 1) / T, T>>>(dst);
    inv_k<<<(NN + T - 1) / T, T>>>();

    // ---- layer 0: NGNN SAGEConv (relu fused into consumers' A-load) ----
    mm_k<128, false, true ><<<GB, T, s128>>>(x, w_self0,  b_self0, p_a, NN);
    mm_k<128, false, false><<<GB, T, s128>>>(x, w_neigh0, nullptr, p_p, NN);
    scatter_k<128><<<(NE * 32 + T - 1) / T, T>>>(p_p, src, dst, p_a);      // p_a = conv0 (pre-relu)
    mm_k<128, true, true><<<GB, T, s128>>>(p_a, fc_w,  fc_b,  p_b, NN);    // relu(conv0) @ fc
    mm_k<128, true, true><<<GB, T, s128>>>(p_b, fc2_w, fc2_b, p_a, NN);    // relu(fc) @ fc2

    // ---- layer 1: SAGEConv ----
    mm_k<128, true, true ><<<GB, T, s128>>>(p_a, w_self1,  b_self1, p_b, NN);
    mm_k<128, true, false><<<GB, T, s128>>>(p_a, w_neigh1, nullptr, p_p, NN);
    scatter_k<128><<<(NE * 32 + T - 1) / T, T>>>(p_p, src, dst, p_b);      // p_b = conv1 (pre-relu)

    // ---- layer 2 (output, width 64) ----
    mm_k<64, true, true ><<<GB, T, s64>>>(p_b, w_self2,  b_self2, out, NN);
    mm_k<64, true, false><<<GB, T, s64>>>(p_b, w_neigh2, nullptr, p_p, NN);
    scatter_k<64><<<(NE * 16 + T - 1) / T, T>>>(p_p, src, dst, out);
}